// round 9
// baseline (speedup 1.0000x reference)
#include <cuda_runtime.h>
#include <cuda_fp16.h>
#include <cuda_fp8.h>
#include <cstdint>

#define NN 8192
#define TT 100

constexpr int TPB  = 256;
constexpr int NBLK = 512;    // 64 col-chunks x 8 row-chunks
constexpr int CCH  = 64;     // col chunks of 128 cols
constexpr int RCH8 = 8;      // row chunks of 1024 rows

// Scratch (device globals: no allocation allowed in kernel_launch)
__device__ __align__(16) unsigned char g_tsA[(size_t)NN * NN]; // tiled e4m3 fragments (64 MB)
__device__ float    g_diag[NN];
__device__ float    g_state[3 * NN];                            // U | I | V (SoA)
__device__ float    g_k[4][3 * NN];
__device__ __align__(16) float g_partial[RCH8 * NN];            // 256 KB
__device__ unsigned g_cnt[CCH];                                 // monotone per replay
__device__ unsigned g_arrive;
__device__ unsigned g_gen;

// ---------------------------------------------------------------------------
// Convert ts -> e4m3, tiled for mma.m16n8k32 A-fragments.
// Tile (i,j): out-cols [16i,16i+16), rows [32j,32j+32). 512 B at ((i*256+j)*512).
// Lane l (g=l>>2, tg=l&3) holds uint4 {a0,a1,a2,a3}:
//   a0 bytes: rows 32j+4tg+0..3, col 16i+g        (k-low,  m=g)
//   a1 bytes: rows 32j+4tg+0..3, col 16i+g+8      (k-low,  m=g+8)
//   a2 bytes: rows 32j+16+4tg+0..3, col 16i+g     (k-high, m=g)
//   a3 bytes: rows 32j+16+4tg+0..3, col 16i+g+8   (k-high, m=g+8)
// ---------------------------------------------------------------------------
__global__ void convert_kernel(const float* __restrict__ ts) {
    __shared__ unsigned sQ[32 * 32];   // 32 rows x 128 cols as bytes
    const int bid  = blockIdx.x;
    const int j    = bid & 255;        // 32-row group
    const int cc   = bid >> 8;         // 128-col chunk
    const int row0 = j * 32, col0 = cc * 128;
    const int tid  = threadIdx.x;

#pragma unroll
    for (int u = 0; u < 4; ++u) {
        int idx = u * 256 + tid;       // 1024 float4s
        int rr  = idx >> 5;            // 32 float4 per row
        int cf  = idx & 31;
        float4 f = *reinterpret_cast<const float4*>(ts + (size_t)(row0 + rr) * NN + col0 + cf * 4);
        __nv_fp8x2_storage_t lo = __nv_cvt_float2_to_fp8x2(
            make_float2(f.x * 8192.f, f.y * 8192.f), __NV_SATFINITE, __NV_E4M3);
        __nv_fp8x2_storage_t hi = __nv_cvt_float2_to_fp8x2(
            make_float2(f.z * 8192.f, f.w * 8192.f), __NV_SATFINITE, __NV_E4M3);
        sQ[rr * 32 + cf] = (unsigned)lo | ((unsigned)hi << 16);
    }
    __syncthreads();

    const int w = tid >> 5, lane = tid & 31, g = lane >> 2, tg = lane & 3;
    const int c = 16 * w + g;
    auto B = [&](int r, int col) -> unsigned {
        return (sQ[r * 32 + (col >> 2)] >> ((col & 3) * 8)) & 0xffu;
    };
    unsigned a0 = B(4*tg+0, c)      | (B(4*tg+1, c)      << 8) | (B(4*tg+2, c)      << 16) | (B(4*tg+3, c)      << 24);
    unsigned a1 = B(4*tg+0, c+8)    | (B(4*tg+1, c+8)    << 8) | (B(4*tg+2, c+8)    << 16) | (B(4*tg+3, c+8)    << 24);
    unsigned a2 = B(16+4*tg+0, c)   | (B(16+4*tg+1, c)   << 8) | (B(16+4*tg+2, c)   << 16) | (B(16+4*tg+3, c)   << 24);
    unsigned a3 = B(16+4*tg+0, c+8) | (B(16+4*tg+1, c+8) << 8) | (B(16+4*tg+2, c+8) << 16) | (B(16+4*tg+3, c+8) << 24);

    const int i_tile = cc * 8 + w;
    size_t addr = ((size_t)i_tile * 256 + j) * 512 + (size_t)lane * 16;
    *reinterpret_cast<uint4*>(g_tsA + addr) = make_uint4(a0, a1, a2, a3);
}

__global__ void init_kernel(const float* __restrict__ x0,
                            const float* __restrict__ ts,
                            float* __restrict__ out) {
    int i = blockIdx.x * blockDim.x + threadIdx.x;
    if (i < NN) {
        g_state[i]          = fabsf(x0[3 * i + 0]);
        g_state[NN + i]     = fabsf(x0[3 * i + 1]);
        g_state[2 * NN + i] = fabsf(x0[3 * i + 2]);
        float d = ts[(size_t)i * NN + i] * 8192.f;
        __nv_fp8_storage_t s8 = __nv_cvt_float_to_fp8(d, __NV_SATFINITE, __NV_E4M3);
        __half_raw hr = __nv_cvt_fp8_to_halfraw(s8, __NV_E4M3);
        g_diag[i] = __half2float(__half(hr)) * (1.f / 8192.f);
    }
    if (i < 3 * TT) out[i] = 0.f;
    if (i < CCH)    g_cnt[i] = 0u;
    if (i == 0)     { g_arrive = 0u; g_gen = 0u; }
}

__device__ __forceinline__ float sigmoidf_(float z) {
    return 1.f / (1.f + expf(-z));
}

__global__ void out0_kernel(const float* __restrict__ W, const float* __restrict__ bb,
                            const float* __restrict__ slope, const float* __restrict__ thr,
                            float* __restrict__ out) {
    int i = blockIdx.x * blockDim.x + threadIdx.x;
    float U = g_state[i], I = g_state[NN + i], V = g_state[2 * NN + i];
    float s[3];
#pragma unroll
    for (int m = 0; m < 3; ++m) {
        float lin = W[3 * m + 0] * U + W[3 * m + 1] * I + W[3 * m + 2] * V + bb[m];
        s[m] = sigmoidf_(slope[m] * (lin - thr[m]));
    }
#pragma unroll
    for (int o = 16; o > 0; o >>= 1) {
        s[0] += __shfl_down_sync(0xffffffffu, s[0], o);
        s[1] += __shfl_down_sync(0xffffffffu, s[1], o);
        s[2] += __shfl_down_sync(0xffffffffu, s[2], o);
    }
    __shared__ float red[3][8];
    int warp = threadIdx.x >> 5, lane = threadIdx.x & 31;
    if (lane == 0) { red[0][warp] = s[0]; red[1][warp] = s[1]; red[2][warp] = s[2]; }
    __syncthreads();
    if (threadIdx.x == 0) {
        float t0 = 0.f, t1 = 0.f, t2 = 0.f;
#pragma unroll
        for (int w = 0; w < 8; ++w) { t0 += red[0][w]; t1 += red[1][w]; t2 += red[2][w]; }
        atomicAdd(out + 0 * TT, t0 * (1.f / 8192.f));
        atomicAdd(out + 1 * TT, t1 * (1.f / 8192.f));
        atomicAdd(out + 2 * TT, t2 * (1.f / 8192.f));
    }
}

__device__ __forceinline__ void mma_e4m3(float& c0, float& c1, float& c2, float& c3,
                                         const uint4& a, unsigned b0, unsigned b1) {
    asm volatile(
        "mma.sync.aligned.m16n8k32.row.col.f32.e4m3.e4m3.f32 "
        "{%0,%1,%2,%3}, {%4,%5,%6,%7}, {%8,%9}, {%0,%1,%2,%3};\n"
        : "+f"(c0), "+f"(c1), "+f"(c2), "+f"(c3)
        : "r"(a.x), "r"(a.y), "r"(a.z), "r"(a.w), "r"(b0), "r"(b1));
}

// Grid-wide barrier (all NBLK blocks co-resident by construction).
__device__ __forceinline__ void grid_barrier(unsigned gen) {
    __syncthreads();
    if (threadIdx.x == 0) {
        __threadfence();
        unsigned old = atomicAdd(&g_arrive, 1u);
        if (old == NBLK - 1) {
            g_arrive = 0u;
            __threadfence();
            atomicExch(&g_gen, gen);
        } else {
            unsigned cur;
            do {
                asm volatile("ld.global.acquire.gpu.u32 %0, [%1];" : "=r"(cur) : "l"(&g_gen));
            } while (cur < gen);
        }
    }
    __syncthreads();
}

// ---------------------------------------------------------------------------
// Fully persistent solver: all 99 RK4 steps. Per stage:
//   quantize V chunk -> smem (e4m3 packed)
//   Phase A: each warp, 32x m16n8k32 MMA over its 16 cols x 1024 rows
//   counter wait, Phase B: 16 threads reduce 8 partials + RHS for 16 cols
//   grid barrier
// ---------------------------------------------------------------------------
__global__ void __launch_bounds__(TPB, 4) solve_kernel(
    const float* __restrict__ times,
    const float* __restrict__ betas, const float* __restrict__ deltas,
    const float* __restrict__ cs, const float* __restrict__ ps,
    const float* __restrict__ W, const float* __restrict__ bb,
    const float* __restrict__ slope, const float* __restrict__ thr,
    float* __restrict__ out) {

    const int tid  = threadIdx.x;
    const int ci   = blockIdx.x & 63;
    const int ri   = blockIdx.x >> 6;
    const int col0 = ci * 128;
    const int row0 = ri * 1024;
    const int w = tid >> 5, lane = tid & 31, g = lane >> 2, tg = lane & 3;
    const int pbcol0  = blockIdx.x * 16;     // Phase-B columns
    const int pbchunk = blockIdx.x >> 3;

    __shared__ unsigned sVq[256];

    // Warp's A-fragment stream: tile (ci*8+w, ri*32 + jj), lane offset
    const uint4* tbase = reinterpret_cast<const uint4*>(g_tsA)
        + ((size_t)(ci * 8 + w) * 256 + ri * 32) * 32 + lane;

    for (int step = 0; step < TT - 1; ++step) {
        const float h   = times[step + 1] - times[step];
        const float hd6 = h * (1.f / 6.f);

        for (int stage = 1; stage <= 4; ++stage) {
            const float ah = (stage == 1) ? 0.f : ((stage == 4) ? h : 0.5f * h);
            const float* kprev = g_k[(stage >= 2) ? (stage - 2) : 0];
            float* kcur = g_k[stage - 1];

            // ---- quantize V chunk to packed e4m3 ----
            {
                int r = row0 + tid * 4;
                float4 v = *reinterpret_cast<const float4*>(g_state + 2 * NN + r);
                if (stage > 1) {
                    float4 kp = *reinterpret_cast<const float4*>(kprev + 2 * NN + r);
                    v.x = fmaf(ah, kp.x, v.x);
                    v.y = fmaf(ah, kp.y, v.y);
                    v.z = fmaf(ah, kp.z, v.z);
                    v.w = fmaf(ah, kp.w, v.w);
                }
                __nv_fp8x2_storage_t lo = __nv_cvt_float2_to_fp8x2(
                    make_float2(v.x, v.y), __NV_SATFINITE, __NV_E4M3);
                __nv_fp8x2_storage_t hi = __nv_cvt_float2_to_fp8x2(
                    make_float2(v.z, v.w), __NV_SATFINITE, __NV_E4M3);
                sVq[tid] = (unsigned)lo | ((unsigned)hi << 16);
            }
            __syncthreads();

            // ---- Phase A: 32 MMAs over row tiles ----
            float c0 = 0.f, c1 = 0.f, c2 = 0.f, c3 = 0.f;
            uint4 q[4];
#pragma unroll
            for (int b = 0; b < 4; ++b) q[b] = tbase[(size_t)b * 32];
#pragma unroll
            for (int it = 0; it < 8; ++it) {
                uint4 cur[4];
#pragma unroll
                for (int b = 0; b < 4; ++b) cur[b] = q[b];
                if (it < 7) {
#pragma unroll
                    for (int b = 0; b < 4; ++b) q[b] = tbase[(size_t)((it + 1) * 4 + b) * 32];
                }
#pragma unroll
                for (int b = 0; b < 4; ++b) {
                    int jj = it * 4 + b;
                    unsigned b0 = sVq[jj * 8 + tg];
                    unsigned b1 = sVq[jj * 8 + 4 + tg];
                    mma_e4m3(c0, c1, c2, c3, cur[b], b0, b1);
                }
            }
            if (tg == 0) {
                g_partial[ri * NN + col0 + w * 16 + g]     = c0;
                g_partial[ri * NN + col0 + w * 16 + g + 8] = c2;
            }

            __threadfence();
            __syncthreads();
            if (tid == 0) atomicAdd(&g_cnt[ci], 1u);

            // wait for this block's Phase-B chunk (8 row-blocks)
            const unsigned tgt = (unsigned)(step * 4 + stage) * 8u;
            if (tid == 0) {
                unsigned cur;
                do {
                    asm volatile("ld.global.acquire.gpu.u32 %0, [%1];" : "=r"(cur) : "l"(&g_cnt[pbchunk]));
                } while (cur < tgt);
            }
            __syncthreads();

            // ---- Phase B: reduce 8 partials + RHS for 16 columns ----
            float s0 = 0.f, s1 = 0.f, s2 = 0.f;
            if (tid < 16) {
                int i = pbcol0 + tid;
                float coup = 0.f;
#pragma unroll
                for (int rr = 0; rr < 8; ++rr) coup += g_partial[rr * NN + i];

                float U = g_state[i], I = g_state[NN + i], V = g_state[2 * NN + i];
                if (stage > 1) {
                    U = fmaf(ah, kprev[i], U);
                    I = fmaf(ah, kprev[NN + i], I);
                    V = fmaf(ah, kprev[2 * NN + i], V);
                }
                float cp  = coup * (1.f / 8192.f) - g_diag[i] * V;
                float inf = fabsf(betas[i]) * U * V;
                float kU  = -inf;
                float kI  = inf - fabsf(deltas[i]) * I;
                float kV  = fabsf(ps[i]) * I - fabsf(cs[i]) * V + cp;
                kcur[i]          = kU;
                kcur[NN + i]     = kI;
                kcur[2 * NN + i] = kV;

                if (stage == 4) {
                    float nU = g_state[i]          + hd6 * (g_k[0][i]          + 2.f * g_k[1][i]          + 2.f * g_k[2][i]          + kU);
                    float nI = g_state[NN + i]     + hd6 * (g_k[0][NN + i]     + 2.f * g_k[1][NN + i]     + 2.f * g_k[2][NN + i]     + kI);
                    float nV = g_state[2 * NN + i] + hd6 * (g_k[0][2 * NN + i] + 2.f * g_k[1][2 * NN + i] + 2.f * g_k[2][2 * NN + i] + kV);
                    g_state[i]          = nU;
                    g_state[NN + i]     = nI;
                    g_state[2 * NN + i] = nV;
#pragma unroll
                    for (int m = 0; m < 3; ++m) {
                        float lin = W[3 * m + 0] * nU + W[3 * m + 1] * nI + W[3 * m + 2] * nV + bb[m];
                        float sg  = sigmoidf_(slope[m] * (lin - thr[m]));
                        if (m == 0) s0 += sg; else if (m == 1) s1 += sg; else s2 += sg;
                    }
                }
            }
            if (stage == 4 && tid < 16) {
#pragma unroll
                for (int o = 8; o > 0; o >>= 1) {
                    s0 += __shfl_down_sync(0xffffu, s0, o);
                    s1 += __shfl_down_sync(0xffffu, s1, o);
                    s2 += __shfl_down_sync(0xffffu, s2, o);
                }
                if (tid == 0) {
                    atomicAdd(out + 0 * TT + step + 1, s0 * (1.f / 8192.f));
                    atomicAdd(out + 1 * TT + step + 1, s1 * (1.f / 8192.f));
                    atomicAdd(out + 2 * TT + step + 1, s2 * (1.f / 8192.f));
                }
            }

            // stage boundary
            if (!(step == TT - 2 && stage == 4))
                grid_barrier((unsigned)(step * 4 + stage));
        }
    }
}

// ---------------------------------------------------------------------------
extern "C" void kernel_launch(void* const* d_in, const int* in_sizes, int n_in,
                              void* d_out, int out_size) {
    const float* times  = (const float*)d_in[0];
    const float* x0     = (const float*)d_in[1];
    const float* betas  = (const float*)d_in[2];
    const float* deltas = (const float*)d_in[3];
    const float* cs     = (const float*)d_in[4];
    const float* ps     = (const float*)d_in[5];
    const float* ts     = (const float*)d_in[6];
    const float* W      = (const float*)d_in[7];
    const float* b      = (const float*)d_in[8];
    const float* slope  = (const float*)d_in[9];
    const float* thr    = (const float*)d_in[10];
    float* out = (float*)d_out;

    convert_kernel<<<256 * 64, 256>>>(ts);
    init_kernel<<<NN / 256, 256>>>(x0, ts, out);
    out0_kernel<<<NN / 256, 256>>>(W, b, slope, thr, out);
    solve_kernel<<<NBLK, TPB>>>(times, betas, deltas, cs, ps, W, b, slope, thr, out);
}

// round 10
// speedup vs baseline: 1.2501x; 1.2501x over previous
#include <cuda_runtime.h>
#include <cuda_fp16.h>
#include <cuda_fp8.h>
#include <cstdint>

#define NN 8192
#define TT 100

constexpr int TPB  = 256;
constexpr int NBLK = 512;    // 512 blocks x 16 cols, full K per block

// Scratch (device globals: no allocation allowed in kernel_launch)
__device__ __align__(16) unsigned char g_tsA[(size_t)NN * NN]; // tiled e4m3 fragments (64 MB)
__device__ __align__(16) unsigned char g_Vq[NN];               // e4m3 stage-V vector
__device__ float    g_diag[NN];
__device__ float    g_state[3 * NN];                            // U | I | V (SoA)
__device__ float    g_k[4][3 * NN];
__device__ unsigned g_arrive;
__device__ unsigned g_gen;

// ---------------------------------------------------------------------------
// Convert ts -> e4m3, tiled for mma.m16n8k32 A-fragments.
// Tile (i,j): out-cols [16i,16i+16), rows [32j,32j+32). 512 B at ((i*256+j)*512).
// Lane l (g=l>>2, tg=l&3) holds uint4 {a0,a1,a2,a3}:
//   a0: rows 32j+4tg+0..3, col 16i+g; a1: same rows, col 16i+g+8
//   a2: rows 32j+16+4tg+0..3, col 16i+g; a3: same rows, col 16i+g+8
// ---------------------------------------------------------------------------
__global__ void convert_kernel(const float* __restrict__ ts) {
    __shared__ unsigned sQ[32 * 32];   // 32 rows x 128 cols as bytes
    const int bid  = blockIdx.x;
    const int j    = bid & 255;        // 32-row group
    const int cc   = bid >> 8;         // 128-col chunk
    const int row0 = j * 32, col0 = cc * 128;
    const int tid  = threadIdx.x;

#pragma unroll
    for (int u = 0; u < 4; ++u) {
        int idx = u * 256 + tid;       // 1024 float4s
        int rr  = idx >> 5;
        int cf  = idx & 31;
        float4 f = *reinterpret_cast<const float4*>(ts + (size_t)(row0 + rr) * NN + col0 + cf * 4);
        __nv_fp8x2_storage_t lo = __nv_cvt_float2_to_fp8x2(
            make_float2(f.x * 8192.f, f.y * 8192.f), __NV_SATFINITE, __NV_E4M3);
        __nv_fp8x2_storage_t hi = __nv_cvt_float2_to_fp8x2(
            make_float2(f.z * 8192.f, f.w * 8192.f), __NV_SATFINITE, __NV_E4M3);
        sQ[rr * 32 + cf] = (unsigned)lo | ((unsigned)hi << 16);
    }
    __syncthreads();

    const int w = tid >> 5, lane = tid & 31, g = lane >> 2, tg = lane & 3;
    const int c = 16 * w + g;
    auto B = [&](int r, int col) -> unsigned {
        return (sQ[r * 32 + (col >> 2)] >> ((col & 3) * 8)) & 0xffu;
    };
    unsigned a0 = B(4*tg+0, c)      | (B(4*tg+1, c)      << 8) | (B(4*tg+2, c)      << 16) | (B(4*tg+3, c)      << 24);
    unsigned a1 = B(4*tg+0, c+8)    | (B(4*tg+1, c+8)    << 8) | (B(4*tg+2, c+8)    << 16) | (B(4*tg+3, c+8)    << 24);
    unsigned a2 = B(16+4*tg+0, c)   | (B(16+4*tg+1, c)   << 8) | (B(16+4*tg+2, c)   << 16) | (B(16+4*tg+3, c)   << 24);
    unsigned a3 = B(16+4*tg+0, c+8) | (B(16+4*tg+1, c+8) << 8) | (B(16+4*tg+2, c+8) << 16) | (B(16+4*tg+3, c+8) << 24);

    const int i_tile = cc * 8 + w;
    size_t addr = ((size_t)i_tile * 256 + j) * 512 + (size_t)lane * 16;
    *reinterpret_cast<uint4*>(g_tsA + addr) = make_uint4(a0, a1, a2, a3);
}

__global__ void init_kernel(const float* __restrict__ x0,
                            const float* __restrict__ ts,
                            float* __restrict__ out) {
    int i = blockIdx.x * blockDim.x + threadIdx.x;
    if (i < NN) {
        float V0 = fabsf(x0[3 * i + 2]);
        g_state[i]          = fabsf(x0[3 * i + 0]);
        g_state[NN + i]     = fabsf(x0[3 * i + 1]);
        g_state[2 * NN + i] = V0;
        g_Vq[i] = (unsigned char)__nv_cvt_float_to_fp8(V0, __NV_SATFINITE, __NV_E4M3);
        float d = ts[(size_t)i * NN + i] * 8192.f;
        __nv_fp8_storage_t s8 = __nv_cvt_float_to_fp8(d, __NV_SATFINITE, __NV_E4M3);
        __half_raw hr = __nv_cvt_fp8_to_halfraw(s8, __NV_E4M3);
        g_diag[i] = __half2float(__half(hr)) * (1.f / 8192.f);
    }
    if (i < 3 * TT) out[i] = 0.f;
    if (i == 0)     { g_arrive = 0u; g_gen = 0u; }
}

__device__ __forceinline__ float sigmoidf_(float z) {
    return 1.f / (1.f + expf(-z));
}

__global__ void out0_kernel(const float* __restrict__ W, const float* __restrict__ bb,
                            const float* __restrict__ slope, const float* __restrict__ thr,
                            float* __restrict__ out) {
    int i = blockIdx.x * blockDim.x + threadIdx.x;
    float U = g_state[i], I = g_state[NN + i], V = g_state[2 * NN + i];
    float s[3];
#pragma unroll
    for (int m = 0; m < 3; ++m) {
        float lin = W[3 * m + 0] * U + W[3 * m + 1] * I + W[3 * m + 2] * V + bb[m];
        s[m] = sigmoidf_(slope[m] * (lin - thr[m]));
    }
#pragma unroll
    for (int o = 16; o > 0; o >>= 1) {
        s[0] += __shfl_down_sync(0xffffffffu, s[0], o);
        s[1] += __shfl_down_sync(0xffffffffu, s[1], o);
        s[2] += __shfl_down_sync(0xffffffffu, s[2], o);
    }
    __shared__ float red[3][8];
    int warp = threadIdx.x >> 5, lane = threadIdx.x & 31;
    if (lane == 0) { red[0][warp] = s[0]; red[1][warp] = s[1]; red[2][warp] = s[2]; }
    __syncthreads();
    if (threadIdx.x == 0) {
        float t0 = 0.f, t1 = 0.f, t2 = 0.f;
#pragma unroll
        for (int w = 0; w < 8; ++w) { t0 += red[0][w]; t1 += red[1][w]; t2 += red[2][w]; }
        atomicAdd(out + 0 * TT, t0 * (1.f / 8192.f));
        atomicAdd(out + 1 * TT, t1 * (1.f / 8192.f));
        atomicAdd(out + 2 * TT, t2 * (1.f / 8192.f));
    }
}

__device__ __forceinline__ void mma_e4m3(float& c0, float& c1, float& c2, float& c3,
                                         const uint4& a, unsigned b0, unsigned b1) {
    asm volatile(
        "mma.sync.aligned.m16n8k32.row.col.f32.e4m3.e4m3.f32 "
        "{%0,%1,%2,%3}, {%4,%5,%6,%7}, {%8,%9}, {%0,%1,%2,%3};\n"
        : "+f"(c0), "+f"(c1), "+f"(c2), "+f"(c3)
        : "r"(a.x), "r"(a.y), "r"(a.z), "r"(a.w), "r"(b0), "r"(b1));
}

// Grid-wide barrier (all NBLK blocks co-resident by construction).
__device__ __forceinline__ void grid_barrier(unsigned gen) {
    __syncthreads();
    if (threadIdx.x == 0) {
        __threadfence();
        unsigned old = atomicAdd(&g_arrive, 1u);
        if (old == NBLK - 1) {
            g_arrive = 0u;
            __threadfence();
            atomicExch(&g_gen, gen);
        } else {
            unsigned cur;
            do {
                asm volatile("ld.global.acquire.gpu.u32 %0, [%1];" : "=r"(cur) : "l"(&g_gen));
            } while (cur < gen);
        }
    }
    __syncthreads();
}

// ---------------------------------------------------------------------------
// Persistent solver. Block b owns cols [16b,16b+16) over FULL K (8192 rows).
// Per stage: load g_Vq -> smem; 8 warps x 32 MMAs (each warp 1024 rows);
// intra-block reduce; 16 threads do RHS + write kcur + write next g_Vq;
// ONE grid barrier.
// ---------------------------------------------------------------------------
__global__ void __launch_bounds__(TPB, 4) solve_kernel(
    const float* __restrict__ times,
    const float* __restrict__ betas, const float* __restrict__ deltas,
    const float* __restrict__ cs, const float* __restrict__ ps,
    const float* __restrict__ W, const float* __restrict__ bb,
    const float* __restrict__ slope, const float* __restrict__ thr,
    float* __restrict__ out) {

    const int tid  = threadIdx.x;
    const int bid  = blockIdx.x;
    const int w = tid >> 5, lane = tid & 31, g = lane >> 2, tg = lane & 3;

    __shared__ uint4 sVq4[512];       // full 8192-byte Vq vector
    __shared__ float sC[8][17];       // per-warp partial C (16 cols)

    unsigned* sVq32 = reinterpret_cast<unsigned*>(sVq4);

    // Warp's contiguous fragment stream: tiles (bid, w*32 .. w*32+31)
    const uint4* mp = reinterpret_cast<const uint4*>(g_tsA)
        + ((size_t)bid * 256 + w * 32) * 32 + lane;
    const int vbase = w * 256;        // u32 index of this warp's 1024 rows

    for (int step = 0; step < TT - 1; ++step) {
        const float h   = times[step + 1] - times[step];
        const float hd6 = h * (1.f / 6.f);

        for (int stage = 1; stage <= 4; ++stage) {
            const float ah = (stage == 1) ? 0.f : ((stage == 4) ? h : 0.5f * h);
            const float* kprev = g_k[(stage >= 2) ? (stage - 2) : 0];
            float* kcur = g_k[stage - 1];

            // ---- load quantized V vector into smem ----
            {
                const uint4* gv = reinterpret_cast<const uint4*>(g_Vq);
                sVq4[tid]       = gv[tid];
                sVq4[tid + 256] = gv[tid + 256];
            }
            __syncthreads();

            // ---- Phase A: 32 MMAs, consume-then-refill prefetch ring of 8 ----
            float c0 = 0.f, c1 = 0.f, c2 = 0.f, c3 = 0.f;
            uint4 q[8];
#pragma unroll
            for (int b = 0; b < 8; ++b) q[b] = mp[(size_t)b * 32];
#pragma unroll
            for (int it = 0; it < 4; ++it) {
#pragma unroll
                for (int b = 0; b < 8; ++b) {
                    uint4 cu = q[b];
                    if (it < 3) q[b] = mp[(size_t)((it + 1) * 8 + b) * 32];
                    int jj = it * 8 + b;
                    unsigned b0 = sVq32[vbase + jj * 8 + tg];
                    unsigned b1 = sVq32[vbase + jj * 8 + 4 + tg];
                    mma_e4m3(c0, c1, c2, c3, cu, b0, b1);
                }
            }
            if (tg == 0) { sC[w][g] = c0; sC[w][g + 8] = c2; }
            __syncthreads();

            // ---- Phase B: 16 threads, one column each ----
            float s0 = 0.f, s1 = 0.f, s2 = 0.f;
            if (tid < 16) {
                const int i = bid * 16 + tid;
                float coup = 0.f;
#pragma unroll
                for (int ww = 0; ww < 8; ++ww) coup += sC[ww][tid];

                float U = g_state[i], I = g_state[NN + i], V = g_state[2 * NN + i];
                if (stage > 1) {
                    U = fmaf(ah, kprev[i], U);
                    I = fmaf(ah, kprev[NN + i], I);
                    V = fmaf(ah, kprev[2 * NN + i], V);
                }
                float cp  = coup * (1.f / 8192.f) - g_diag[i] * V;
                float inf = fabsf(betas[i]) * U * V;
                float kU  = -inf;
                float kI  = inf - fabsf(deltas[i]) * I;
                float kV  = fabsf(ps[i]) * I - fabsf(cs[i]) * V + cp;
                kcur[i]          = kU;
                kcur[NN + i]     = kI;
                kcur[2 * NN + i] = kV;

                float vnext;
                if (stage < 4) {
                    float an = (stage == 3) ? h : 0.5f * h;   // a for next stage
                    vnext = fmaf(an, kV, g_state[2 * NN + i]);
                } else {
                    float nU = g_state[i]          + hd6 * (g_k[0][i]          + 2.f * g_k[1][i]          + 2.f * g_k[2][i]          + kU);
                    float nI = g_state[NN + i]     + hd6 * (g_k[0][NN + i]     + 2.f * g_k[1][NN + i]     + 2.f * g_k[2][NN + i]     + kI);
                    float nV = g_state[2 * NN + i] + hd6 * (g_k[0][2 * NN + i] + 2.f * g_k[1][2 * NN + i] + 2.f * g_k[2][2 * NN + i] + kV);
                    g_state[i]          = nU;
                    g_state[NN + i]     = nI;
                    g_state[2 * NN + i] = nV;
                    vnext = nV;
#pragma unroll
                    for (int m = 0; m < 3; ++m) {
                        float lin = W[3 * m + 0] * nU + W[3 * m + 1] * nI + W[3 * m + 2] * nV + bb[m];
                        float sg  = sigmoidf_(slope[m] * (lin - thr[m]));
                        if (m == 0) s0 += sg; else if (m == 1) s1 += sg; else s2 += sg;
                    }
                }
                g_Vq[i] = (unsigned char)__nv_cvt_float_to_fp8(vnext, __NV_SATFINITE, __NV_E4M3);
            }

            if (stage == 4 && tid < 16) {
#pragma unroll
                for (int o = 8; o > 0; o >>= 1) {
                    s0 += __shfl_down_sync(0xffffu, s0, o);
                    s1 += __shfl_down_sync(0xffffu, s1, o);
                    s2 += __shfl_down_sync(0xffffu, s2, o);
                }
                if (tid == 0) {
                    atomicAdd(out + 0 * TT + step + 1, s0 * (1.f / 8192.f));
                    atomicAdd(out + 1 * TT + step + 1, s1 * (1.f / 8192.f));
                    atomicAdd(out + 2 * TT + step + 1, s2 * (1.f / 8192.f));
                }
            }

            // single stage boundary sync
            if (!(step == TT - 2 && stage == 4))
                grid_barrier((unsigned)(step * 4 + stage));
        }
    }
}

// ---------------------------------------------------------------------------
extern "C" void kernel_launch(void* const* d_in, const int* in_sizes, int n_in,
                              void* d_out, int out_size) {
    const float* times  = (const float*)d_in[0];
    const float* x0     = (const float*)d_in[1];
    const float* betas  = (const float*)d_in[2];
    const float* deltas = (const float*)d_in[3];
    const float* cs     = (const float*)d_in[4];
    const float* ps     = (const float*)d_in[5];
    const float* ts     = (const float*)d_in[6];
    const float* W      = (const float*)d_in[7];
    const float* b      = (const float*)d_in[8];
    const float* slope  = (const float*)d_in[9];
    const float* thr    = (const float*)d_in[10];
    float* out = (float*)d_out;

    convert_kernel<<<256 * 64, 256>>>(ts);
    init_kernel<<<NN / 256, 256>>>(x0, ts, out);
    out0_kernel<<<NN / 256, 256>>>(W, b, slope, thr, out);
    solve_kernel<<<NBLK, TPB>>>(times, betas, deltas, cs, ps, W, b, slope, thr, out);
}

// round 11
// speedup vs baseline: 1.2808x; 1.0246x over previous
#include <cuda_runtime.h>
#include <cuda_fp16.h>
#include <cuda_fp8.h>
#include <cstdint>

#define NN 8192
#define TT 100

constexpr int TPB  = 256;
constexpr int NBLK = 512;    // 512 blocks x 16 cols, full K per block

// Scratch (device globals: no allocation allowed in kernel_launch)
__device__ __align__(16) unsigned char g_tsA[(size_t)NN * NN]; // tiled e4m3 fragments (64 MB)
__device__ __align__(16) unsigned char g_Vq[NN];               // e4m3 stage-V vector
__device__ float    g_diag[NN];
__device__ float    g_state[3 * NN];                            // initial U | I | V (SoA)
__device__ unsigned g_arrive;
__device__ unsigned g_gen;

// ---------------------------------------------------------------------------
// Convert ts -> e4m3, tiled for mma.m16n8k32 A-fragments. (unchanged, verified)
// ---------------------------------------------------------------------------
__global__ void convert_kernel(const float* __restrict__ ts) {
    __shared__ unsigned sQ[32 * 32];   // 32 rows x 128 cols as bytes
    const int bid  = blockIdx.x;
    const int j    = bid & 255;        // 32-row group
    const int cc   = bid >> 8;         // 128-col chunk
    const int row0 = j * 32, col0 = cc * 128;
    const int tid  = threadIdx.x;

#pragma unroll
    for (int u = 0; u < 4; ++u) {
        int idx = u * 256 + tid;
        int rr  = idx >> 5;
        int cf  = idx & 31;
        float4 f = *reinterpret_cast<const float4*>(ts + (size_t)(row0 + rr) * NN + col0 + cf * 4);
        __nv_fp8x2_storage_t lo = __nv_cvt_float2_to_fp8x2(
            make_float2(f.x * 8192.f, f.y * 8192.f), __NV_SATFINITE, __NV_E4M3);
        __nv_fp8x2_storage_t hi = __nv_cvt_float2_to_fp8x2(
            make_float2(f.z * 8192.f, f.w * 8192.f), __NV_SATFINITE, __NV_E4M3);
        sQ[rr * 32 + cf] = (unsigned)lo | ((unsigned)hi << 16);
    }
    __syncthreads();

    const int w = tid >> 5, lane = tid & 31, g = lane >> 2, tg = lane & 3;
    const int c = 16 * w + g;
    auto B = [&](int r, int col) -> unsigned {
        return (sQ[r * 32 + (col >> 2)] >> ((col & 3) * 8)) & 0xffu;
    };
    unsigned a0 = B(4*tg+0, c)      | (B(4*tg+1, c)      << 8) | (B(4*tg+2, c)      << 16) | (B(4*tg+3, c)      << 24);
    unsigned a1 = B(4*tg+0, c+8)    | (B(4*tg+1, c+8)    << 8) | (B(4*tg+2, c+8)    << 16) | (B(4*tg+3, c+8)    << 24);
    unsigned a2 = B(16+4*tg+0, c)   | (B(16+4*tg+1, c)   << 8) | (B(16+4*tg+2, c)   << 16) | (B(16+4*tg+3, c)   << 24);
    unsigned a3 = B(16+4*tg+0, c+8) | (B(16+4*tg+1, c+8) << 8) | (B(16+4*tg+2, c+8) << 16) | (B(16+4*tg+3, c+8) << 24);

    const int i_tile = cc * 8 + w;
    size_t addr = ((size_t)i_tile * 256 + j) * 512 + (size_t)lane * 16;
    *reinterpret_cast<uint4*>(g_tsA + addr) = make_uint4(a0, a1, a2, a3);
}

__global__ void init_kernel(const float* __restrict__ x0,
                            const float* __restrict__ ts,
                            float* __restrict__ out) {
    int i = blockIdx.x * blockDim.x + threadIdx.x;
    if (i < NN) {
        float V0 = fabsf(x0[3 * i + 2]);
        g_state[i]          = fabsf(x0[3 * i + 0]);
        g_state[NN + i]     = fabsf(x0[3 * i + 1]);
        g_state[2 * NN + i] = V0;
        g_Vq[i] = (unsigned char)__nv_cvt_float_to_fp8(V0, __NV_SATFINITE, __NV_E4M3);
        float d = ts[(size_t)i * NN + i] * 8192.f;
        __nv_fp8_storage_t s8 = __nv_cvt_float_to_fp8(d, __NV_SATFINITE, __NV_E4M3);
        __half_raw hr = __nv_cvt_fp8_to_halfraw(s8, __NV_E4M3);
        g_diag[i] = __half2float(__half(hr)) * (1.f / 8192.f);
    }
    if (i < 3 * TT) out[i] = 0.f;
    if (i == 0)     { g_arrive = 0u; g_gen = 0u; }
}

__device__ __forceinline__ float sigmoidf_(float z) {
    return 1.f / (1.f + expf(-z));
}

__global__ void out0_kernel(const float* __restrict__ W, const float* __restrict__ bb,
                            const float* __restrict__ slope, const float* __restrict__ thr,
                            float* __restrict__ out) {
    int i = blockIdx.x * blockDim.x + threadIdx.x;
    float U = g_state[i], I = g_state[NN + i], V = g_state[2 * NN + i];
    float s[3];
#pragma unroll
    for (int m = 0; m < 3; ++m) {
        float lin = W[3 * m + 0] * U + W[3 * m + 1] * I + W[3 * m + 2] * V + bb[m];
        s[m] = sigmoidf_(slope[m] * (lin - thr[m]));
    }
#pragma unroll
    for (int o = 16; o > 0; o >>= 1) {
        s[0] += __shfl_down_sync(0xffffffffu, s[0], o);
        s[1] += __shfl_down_sync(0xffffffffu, s[1], o);
        s[2] += __shfl_down_sync(0xffffffffu, s[2], o);
    }
    __shared__ float red[3][8];
    int warp = threadIdx.x >> 5, lane = threadIdx.x & 31;
    if (lane == 0) { red[0][warp] = s[0]; red[1][warp] = s[1]; red[2][warp] = s[2]; }
    __syncthreads();
    if (threadIdx.x == 0) {
        float t0 = 0.f, t1 = 0.f, t2 = 0.f;
#pragma unroll
        for (int w = 0; w < 8; ++w) { t0 += red[0][w]; t1 += red[1][w]; t2 += red[2][w]; }
        atomicAdd(out + 0 * TT, t0 * (1.f / 8192.f));
        atomicAdd(out + 1 * TT, t1 * (1.f / 8192.f));
        atomicAdd(out + 2 * TT, t2 * (1.f / 8192.f));
    }
}

__device__ __forceinline__ void mma_e4m3(float& c0, float& c1, float& c2, float& c3,
                                         const uint4& a, unsigned b0, unsigned b1) {
    asm volatile(
        "mma.sync.aligned.m16n8k32.row.col.f32.e4m3.e4m3.f32 "
        "{%0,%1,%2,%3}, {%4,%5,%6,%7}, {%8,%9}, {%0,%1,%2,%3};\n"
        : "+f"(c0), "+f"(c1), "+f"(c2), "+f"(c3)
        : "r"(a.x), "r"(a.y), "r"(a.z), "r"(a.w), "r"(b0), "r"(b1));
}

// Grid-wide barrier (all NBLK blocks co-resident by construction).
__device__ __forceinline__ void grid_barrier(unsigned gen) {
    __syncthreads();
    if (threadIdx.x == 0) {
        __threadfence();
        unsigned old = atomicAdd(&g_arrive, 1u);
        if (old == NBLK - 1) {
            g_arrive = 0u;
            __threadfence();
            atomicExch(&g_gen, gen);
        } else {
            unsigned cur;
            do {
                asm volatile("ld.global.acquire.gpu.u32 %0, [%1];" : "=r"(cur) : "l"(&g_gen));
            } while (cur < gen);
        }
    }
    __syncthreads();
}

// ---------------------------------------------------------------------------
// Persistent solver. Block b owns cols [16b,16b+16) over full K.
// State + RK4 k-history live in block-local smem (threads 0..15 own columns).
// Matrix fragment ring prefetches ACROSS the stage barrier (stage-invariant).
// Per stage: warp-local Vq smem fill -> 32 MMAs/warp -> block reduce ->
// Phase B (smem only) -> write g_Vq -> ONE grid barrier.
// ---------------------------------------------------------------------------
__global__ void __launch_bounds__(TPB, 4) solve_kernel(
    const float* __restrict__ times,
    const float* __restrict__ betas, const float* __restrict__ deltas,
    const float* __restrict__ cs, const float* __restrict__ ps,
    const float* __restrict__ W, const float* __restrict__ bb,
    const float* __restrict__ slope, const float* __restrict__ thr,
    float* __restrict__ out) {

    const int tid  = threadIdx.x;
    const int bid  = blockIdx.x;
    const int w = tid >> 5, lane = tid & 31, g = lane >> 2, tg = lane & 3;

    __shared__ uint4 sVq4[512];       // warp w owns uint4 [w*64, w*64+64)
    __shared__ float sC[8][17];       // per-warp partial C (16 cols)
    __shared__ float sU[16], sI[16], sV[16];
    __shared__ float sK[9][16];       // k1..k3 x {U,I,V}
    __shared__ float sPar[5][16];     // |beta|,|delta|,|p|,|c|,diag

    unsigned* sVq32 = reinterpret_cast<unsigned*>(sVq4);

    if (tid < 16) {
        int i = bid * 16 + tid;
        sU[tid] = g_state[i];
        sI[tid] = g_state[NN + i];
        sV[tid] = g_state[2 * NN + i];
        sPar[0][tid] = fabsf(betas[i]);
        sPar[1][tid] = fabsf(deltas[i]);
        sPar[2][tid] = fabsf(ps[i]);
        sPar[3][tid] = fabsf(cs[i]);
        sPar[4][tid] = g_diag[i];
    }

    // Warp's contiguous fragment stream: tiles (bid, w*32 .. w*32+31)
    const uint4* mp = reinterpret_cast<const uint4*>(g_tsA)
        + ((size_t)bid * 256 + w * 32) * 32 + lane;
    const int vbase = w * 256;        // u32 index of this warp's 1024 rows

    // preload fragment ring (stage-invariant stream)
    uint4 q[8];
#pragma unroll
    for (int b = 0; b < 8; ++b) q[b] = mp[(size_t)b * 32];
    __syncthreads();

    for (int step = 0; step < TT - 1; ++step) {
        const float h   = times[step + 1] - times[step];
        const float hd6 = h * (1.f / 6.f);

        for (int stage = 1; stage <= 4; ++stage) {
            const float ah = (stage == 1) ? 0.f : ((stage == 4) ? h : 0.5f * h);

            // ---- warp-local Vq fill (warp w reads only its own slice) ----
            {
                const uint4* gv = reinterpret_cast<const uint4*>(g_Vq);
                sVq4[w * 64 + lane]      = gv[w * 64 + lane];
                sVq4[w * 64 + 32 + lane] = gv[w * 64 + 32 + lane];
                __syncwarp();
            }

            // ---- Phase A: 32 MMAs; ring refill wraps to next stage's tiles ----
            float c0 = 0.f, c1 = 0.f, c2 = 0.f, c3 = 0.f;
#pragma unroll
            for (int it = 0; it < 4; ++it) {
#pragma unroll
                for (int b = 0; b < 8; ++b) {
                    uint4 cu = q[b];
                    q[b] = mp[(size_t)((((it + 1) & 3) * 8 + b)) * 32];
                    int jj = it * 8 + b;
                    unsigned b0 = sVq32[vbase + jj * 8 + tg];
                    unsigned b1 = sVq32[vbase + jj * 8 + 4 + tg];
                    mma_e4m3(c0, c1, c2, c3, cu, b0, b1);
                }
            }
            if (tg == 0) { sC[w][g] = c0; sC[w][g + 8] = c2; }
            __syncthreads();

            // ---- Phase B: 16 threads, one column each, all-smem ----
            float s0 = 0.f, s1 = 0.f, s2 = 0.f;
            if (tid < 16) {
                const int i = bid * 16 + tid;
                float coup = 0.f;
#pragma unroll
                for (int ww = 0; ww < 8; ++ww) coup += sC[ww][tid];

                float U = sU[tid], I = sI[tid], V = sV[tid];
                if (stage > 1) {
                    const int pb = (stage - 2) * 3;
                    U = fmaf(ah, sK[pb + 0][tid], U);
                    I = fmaf(ah, sK[pb + 1][tid], I);
                    V = fmaf(ah, sK[pb + 2][tid], V);
                }
                float cp  = coup * (1.f / 8192.f) - sPar[4][tid] * V;
                float inf = sPar[0][tid] * U * V;
                float kU  = -inf;
                float kI  = inf - sPar[1][tid] * I;
                float kV  = sPar[2][tid] * I - sPar[3][tid] * V + cp;

                float vnext;
                if (stage < 4) {
                    const int cb = (stage - 1) * 3;
                    sK[cb + 0][tid] = kU;
                    sK[cb + 1][tid] = kI;
                    sK[cb + 2][tid] = kV;
                    float an = (stage == 3) ? h : 0.5f * h;   // a for next stage
                    vnext = fmaf(an, kV, sV[tid]);
                } else {
                    float nU = sU[tid] + hd6 * (sK[0][tid] + 2.f * sK[3][tid] + 2.f * sK[6][tid] + kU);
                    float nI = sI[tid] + hd6 * (sK[1][tid] + 2.f * sK[4][tid] + 2.f * sK[7][tid] + kI);
                    float nV = sV[tid] + hd6 * (sK[2][tid] + 2.f * sK[5][tid] + 2.f * sK[8][tid] + kV);
                    sU[tid] = nU;
                    sI[tid] = nI;
                    sV[tid] = nV;
                    vnext = nV;
#pragma unroll
                    for (int m = 0; m < 3; ++m) {
                        float lin = W[3 * m + 0] * nU + W[3 * m + 1] * nI + W[3 * m + 2] * nV + bb[m];
                        float sg  = sigmoidf_(slope[m] * (lin - thr[m]));
                        if (m == 0) s0 += sg; else if (m == 1) s1 += sg; else s2 += sg;
                    }
                }
                g_Vq[i] = (unsigned char)__nv_cvt_float_to_fp8(vnext, __NV_SATFINITE, __NV_E4M3);
            }

            if (stage == 4 && tid < 16) {
#pragma unroll
                for (int o = 8; o > 0; o >>= 1) {
                    s0 += __shfl_down_sync(0xffffu, s0, o);
                    s1 += __shfl_down_sync(0xffffu, s1, o);
                    s2 += __shfl_down_sync(0xffffu, s2, o);
                }
                if (tid == 0) {
                    atomicAdd(out + 0 * TT + step + 1, s0 * (1.f / 8192.f));
                    atomicAdd(out + 1 * TT + step + 1, s1 * (1.f / 8192.f));
                    atomicAdd(out + 2 * TT + step + 1, s2 * (1.f / 8192.f));
                }
            }

            // single stage boundary sync
            if (!(step == TT - 2 && stage == 4))
                grid_barrier((unsigned)(step * 4 + stage));
        }
    }
}

// ---------------------------------------------------------------------------
extern "C" void kernel_launch(void* const* d_in, const int* in_sizes, int n_in,
                              void* d_out, int out_size) {
    const float* times  = (const float*)d_in[0];
    const float* x0     = (const float*)d_in[1];
    const float* betas  = (const float*)d_in[2];
    const float* deltas = (const float*)d_in[3];
    const float* cs     = (const float*)d_in[4];
    const float* ps     = (const float*)d_in[5];
    const float* ts     = (const float*)d_in[6];
    const float* W      = (const float*)d_in[7];
    const float* b      = (const float*)d_in[8];
    const float* slope  = (const float*)d_in[9];
    const float* thr    = (const float*)d_in[10];
    float* out = (float*)d_out;

    convert_kernel<<<256 * 64, 256>>>(ts);
    init_kernel<<<NN / 256, 256>>>(x0, ts, out);
    out0_kernel<<<NN / 256, 256>>>(W, b, slope, thr, out);
    solve_kernel<<<NBLK, TPB>>>(times, betas, deltas, cs, ps, W, b, slope, thr, out);
}